// round 1
// baseline (speedup 1.0000x reference)
#include <cuda_runtime.h>
#include <cuda_bf16.h>

// Problem constants
#define S_DIM 512
#define R_DIM 384
#define C_MSA 64
#define C_OUTER 32
#define C_OUT 128
#define M_DIM (R_DIM * C_OUTER)   // 12288

// Scratch: left/right projections [S][R*32], norm [R][R]
__device__ float g_L[S_DIM * M_DIM];
__device__ float g_R[S_DIM * M_DIM];
__device__ float g_norm[R_DIM * R_DIM];

// ---------------------------------------------------------------------------
// Kernel 1: LayerNorm + left/right projections + mask
// 4 rows (s,r) per block of 256 threads; 64 threads per row.
// ---------------------------------------------------------------------------
__global__ __launch_bounds__(256) void prep_kernel(
    const float* __restrict__ msa, const float* __restrict__ mask,
    const float* __restrict__ gamma, const float* __restrict__ beta,
    const float* __restrict__ wl, const float* __restrict__ wr)
{
    __shared__ float ws[64][65];   // rows 0-31: w_left[o][c], rows 32-63: w_right
    __shared__ float xs[4][64];
    __shared__ float redS[8], redQ[8];

    int tid = threadIdx.x;

    // Stage projection weights (conflict-free padded layout)
    for (int t = tid; t < 2048; t += 256) {
        int o = t >> 6, c = t & 63;
        ws[o][c]      = wl[t];
        ws[32 + o][c] = wr[t];
    }

    int g = tid >> 6;        // row group within block (0..3)
    int c = tid & 63;        // channel
    int row = blockIdx.x * 4 + g;    // linear (s,r), < 196608

    float v = msa[row * 64 + c];

    // two-warp reduction for mean / meansq
    float s = v, q = v * v;
    #pragma unroll
    for (int off = 16; off; off >>= 1) {
        s += __shfl_xor_sync(0xffffffffu, s, off);
        q += __shfl_xor_sync(0xffffffffu, q, off);
    }
    int wid = tid >> 5;
    if ((tid & 31) == 0) { redS[wid] = s; redQ[wid] = q; }
    __syncthreads();

    float S1 = redS[2*g] + redS[2*g + 1];
    float S2 = redQ[2*g] + redQ[2*g + 1];
    float mu  = S1 * (1.0f / 64.0f);
    float var = S2 * (1.0f / 64.0f) - mu * mu;
    float inv = rsqrtf(var + 1e-5f);
    float xn = (v - mu) * inv * gamma[c] + beta[c];
    xs[g][c] = xn;
    __syncthreads();

    // dot: thread c computes output o=c (left) or o=c-32 (right)
    float acc = 0.0f;
    const float* xrow = xs[g];
    #pragma unroll 16
    for (int k = 0; k < 64; k++)
        acc += xrow[k] * ws[c][k];

    acc *= mask[row];

    int s_idx = row / R_DIM;
    int r_idx = row - s_idx * R_DIM;
    int o = c & 31;
    if (c < 32) g_L[s_idx * M_DIM + r_idx * C_OUTER + o] = acc;
    else        g_R[s_idx * M_DIM + r_idx * C_OUTER + o] = acc;
}

// ---------------------------------------------------------------------------
// Kernel 2: norm[b][d] = sum_s mask[s][b] * mask[s][d]
// ---------------------------------------------------------------------------
__global__ __launch_bounds__(256) void norm_kernel(const float* __restrict__ mask)
{
    __shared__ float mb[16][17], md[16][17];
    int tx = threadIdx.x & 15, ty = threadIdx.x >> 4;
    int b0 = blockIdx.x * 16, d0 = blockIdx.y * 16;
    float acc = 0.0f;
    for (int s0 = 0; s0 < S_DIM; s0 += 16) {
        mb[ty][tx] = mask[(s0 + ty) * R_DIM + b0 + tx];
        md[ty][tx] = mask[(s0 + ty) * R_DIM + d0 + tx];
        __syncthreads();
        #pragma unroll
        for (int i = 0; i < 16; i++) acc += mb[i][tx] * md[i][ty];
        __syncthreads();
    }
    g_norm[(b0 + tx) * R_DIM + d0 + ty] = acc;
}

// ---------------------------------------------------------------------------
// Kernel 3: fused outer-product GEMM (128x128x512 tile of L^T R) + W epilogue
// Grid (96, 96); 256 threads; dynamic smem = 128 KB.
//   Phase 1: SGEMM 128x128, K=512, 8x8 register tiles -> acc
//   Phase 2: stash tile to smem Cs[128][128]; contract the 16 (b,d) 32x32
//            blocks with W2[1024][128] as a k'-split-by-4 mini-GEMM,
//            reduce, add bias, divide by (eps + norm), store.
// ---------------------------------------------------------------------------
__global__ __launch_bounds__(256) void gemm_fused_kernel(
    const float* __restrict__ W,      // output_w, [32][32][128] = [1024][128]
    const float* __restrict__ bias,   // [128]
    float* __restrict__ out)          // [384][384][128]
{
    extern __shared__ float buf[];
    float* As = buf;           // [16][128]
    float* Bs = buf + 2048;    // [16][128]

    int tid = threadIdx.x;
    int tx = tid & 15, ty = tid >> 4;
    int m0 = blockIdx.y * 128, n0 = blockIdx.x * 128;

    float acc[8][8];
    #pragma unroll
    for (int i = 0; i < 8; i++)
        #pragma unroll
        for (int j = 0; j < 8; j++) acc[i][j] = 0.0f;

    for (int k0 = 0; k0 < S_DIM; k0 += 16) {
        #pragma unroll
        for (int r = 0; r < 2; r++) {
            int q4 = tid * 2 + r;          // 0..511 float4s
            int row = q4 >> 5;
            int col = (q4 & 31) << 2;
            *(float4*)&As[row * 128 + col] =
                *(const float4*)&g_L[(k0 + row) * M_DIM + m0 + col];
            *(float4*)&Bs[row * 128 + col] =
                *(const float4*)&g_R[(k0 + row) * M_DIM + n0 + col];
        }
        __syncthreads();
        #pragma unroll
        for (int kk = 0; kk < 16; kk++) {
            float4 a0 = *(float4*)&As[kk * 128 + ty * 4];
            float4 a1 = *(float4*)&As[kk * 128 + 64 + ty * 4];
            float4 b0 = *(float4*)&Bs[kk * 128 + tx * 4];
            float4 b1 = *(float4*)&Bs[kk * 128 + 64 + tx * 4];
            float a[8] = {a0.x, a0.y, a0.z, a0.w, a1.x, a1.y, a1.z, a1.w};
            float b[8] = {b0.x, b0.y, b0.z, b0.w, b1.x, b1.y, b1.z, b1.w};
            #pragma unroll
            for (int i = 0; i < 8; i++)
                #pragma unroll
                for (int j = 0; j < 8; j++)
                    acc[i][j] += a[i] * b[j];
        }
        __syncthreads();
    }

    // ---- Phase 2: epilogue ----
    float* Cs = buf;            // [128][128] = 16384 floats (overlaps As/Bs)
    float* Ws = buf + 16384;    // [128][128] staging: 4 ks-slices x 32 rows

    #pragma unroll
    for (int i = 0; i < 8; i++) {
        int m = (i < 4) ? (ty * 4 + i) : (64 + ty * 4 + (i - 4));
        *(float4*)&Cs[m * 128 + tx * 4] =
            make_float4(acc[i][0], acc[i][1], acc[i][2], acc[i][3]);
        *(float4*)&Cs[m * 128 + 64 + tx * 4] =
            make_float4(acc[i][4], acc[i][5], acc[i][6], acc[i][7]);
    }
    __syncthreads();

    // thread decomposition: ks = k'-split (4), pg = pair group (4), q = f lane (16)
    int q  = tid & 15;
    int pg = (tid >> 4) & 3;    // = b_local
    int ks = tid >> 6;

    float acc2[4][8];
    #pragma unroll
    for (int pp = 0; pp < 4; pp++)
        #pragma unroll
        for (int j = 0; j < 8; j++) acc2[pp][j] = 0.0f;

    for (int mstep = 0; mstep < 8; mstep++) {
        // stage Ws[ks][r in 0..31][f]: W row (ks*256 + mstep*32 + r)
        #pragma unroll
        for (int it = 0; it < 16; it++) {
            int t4 = tid + 256 * it;        // 0..4095 float4s
            int rowW = t4 >> 5;             // 0..127
            int col = (t4 & 31) << 2;
            int ksr = rowW >> 5, rr = rowW & 31;
            *(float4*)&Ws[rowW * 128 + col] =
                *(const float4*)&W[(ksr * 256 + mstep * 32 + rr) * 128 + col];
        }
        __syncthreads();

        const float* WsMe = Ws + ks * 32 * 128;
        int kbase = ks * 256 + mstep * 32;
        #pragma unroll 4
        for (int kk = 0; kk < 32; kk++) {
            int kp = kbase + kk;
            int cc = kp >> 5, ee = kp & 31;
            float w[8];
            #pragma unroll
            for (int j = 0; j < 8; j++) w[j] = WsMe[kk * 128 + q + 16 * j];
            #pragma unroll
            for (int pp = 0; pp < 4; pp++) {
                // pair p = pg*4 + pp -> b_local = pg, d_local = pp
                float pv = Cs[(pg * 32 + cc) * 128 + pp * 32 + ee];
                #pragma unroll
                for (int j = 0; j < 8; j++) acc2[pp][j] += pv * w[j];
            }
        }
        __syncthreads();
    }

    // reduce the 4 k'-splits via smem (reuse Ws region: [4][16][128])
    float* red = Ws;
    #pragma unroll
    for (int pp = 0; pp < 4; pp++)
        #pragma unroll
        for (int j = 0; j < 8; j++)
            red[(ks * 16 + pg * 4 + pp) * 128 + q + 16 * j] = acc2[pp][j];
    __syncthreads();

    int p  = tid >> 4;          // 0..15 pair
    int q2 = tid & 15;
    int bl = p >> 2, dl = p & 3;
    int bg = blockIdx.y * 4 + bl;
    int dg = blockIdx.x * 4 + dl;
    float invn = 1.0f / (1e-3f + g_norm[bg * R_DIM + dg]);
    #pragma unroll
    for (int j = 0; j < 8; j++) {
        int f = q2 + 16 * j;
        float v = red[0 * 2048 + p * 128 + f]
                + red[1 * 2048 + p * 128 + f]
                + red[2 * 2048 + p * 128 + f]
                + red[3 * 2048 + p * 128 + f];
        out[(bg * R_DIM + dg) * C_OUT + f] = (v + bias[f]) * invn;
    }
}

// ---------------------------------------------------------------------------
extern "C" void kernel_launch(void* const* d_in, const int* in_sizes, int n_in,
                              void* d_out, int out_size)
{
    const float* msa   = (const float*)d_in[0];
    const float* mask  = (const float*)d_in[1];
    const float* gamma = (const float*)d_in[2];
    const float* beta  = (const float*)d_in[3];
    const float* wl    = (const float*)d_in[4];
    const float* wr    = (const float*)d_in[5];
    const float* W     = (const float*)d_in[6];
    const float* bias  = (const float*)d_in[7];
    float* out = (float*)d_out;

    prep_kernel<<<(S_DIM * R_DIM) / 4, 256>>>(msa, mask, gamma, beta, wl, wr);
    norm_kernel<<<dim3(R_DIM / 16, R_DIM / 16), 256>>>(mask);

    cudaFuncSetAttribute(gemm_fused_kernel,
                         cudaFuncAttributeMaxDynamicSharedMemorySize, 131072);
    gemm_fused_kernel<<<dim3(M_DIM / 128, M_DIM / 128), 256, 131072>>>(W, bias, out);
}

// round 3
// speedup vs baseline: 1.8345x; 1.8345x over previous
#include <cuda_runtime.h>
#include <cuda_bf16.h>

// Problem constants
#define S_DIM 512
#define R_DIM 384
#define C_MSA 64
#define C_OUTER 32
#define C_OUT 128
#define M_DIM (R_DIM * C_OUTER)   // 12288
#define KC_N 8                    // 512 / 64 k-chunks
#define MT_N 96                   // 12288 / 128 m-tiles

// fp32 scratch projections [S][M] (k-major)
__device__ float g_Lf[S_DIM * M_DIM];
__device__ float g_Rf[S_DIM * M_DIM];
__device__ float g_norm[R_DIM * R_DIM];

// Pre-swizzled SW128-style bf16 tiles: [kc][mtile][128 rows x 128B] as uint4
// element (m,k): tile=(k>>6)*96+(m>>7), r=m&127, g16=(k&63)>>3,
// uint4 index within tile = r*8 + (g16 ^ (r&7)), bf16 lane = k&7
__device__ uint4 g_Ahi[KC_N * MT_N * 1024];
__device__ uint4 g_Alo[KC_N * MT_N * 1024];
__device__ uint4 g_Bhi[KC_N * MT_N * 1024];
__device__ uint4 g_Blo[KC_N * MT_N * 1024];

// ---------------------------------------------------------------------------
// helpers
// ---------------------------------------------------------------------------
__device__ __forceinline__ unsigned smem_u32(const void* p) {
    unsigned r;
    asm("{ .reg .u64 t; cvta.to.shared.u64 t, %1; cvt.u32.u64 %0, t; }"
        : "=r"(r) : "l"(p));
    return r;
}
__device__ __forceinline__ void cp16(unsigned dst, const void* src) {
    asm volatile("cp.async.cg.shared.global [%0], [%1], 16;"
                 :: "r"(dst), "l"(src) : "memory");
}
#define CP_COMMIT() asm volatile("cp.async.commit_group;" ::: "memory")
#define CP_WAIT1()  asm volatile("cp.async.wait_group 1;" ::: "memory")
#define CP_WAIT0()  asm volatile("cp.async.wait_group 0;" ::: "memory")

__device__ __forceinline__ void ldsm4(unsigned* r, unsigned addr) {
    asm volatile("ldmatrix.sync.aligned.m8n8.x4.shared.b16 {%0,%1,%2,%3}, [%4];"
                 : "=r"(r[0]), "=r"(r[1]), "=r"(r[2]), "=r"(r[3]) : "r"(addr));
}
__device__ __forceinline__ void mma16816(float* c, const unsigned* a,
                                         unsigned b0, unsigned b1) {
    asm volatile("mma.sync.aligned.m16n8k16.row.col.f32.bf16.bf16.f32 "
                 "{%0,%1,%2,%3}, {%4,%5,%6,%7}, {%8,%9}, {%0,%1,%2,%3};"
                 : "+f"(c[0]), "+f"(c[1]), "+f"(c[2]), "+f"(c[3])
                 : "r"(a[0]), "r"(a[1]), "r"(a[2]), "r"(a[3]),
                   "r"(b0), "r"(b1));
}

// ---------------------------------------------------------------------------
// Kernel 1: LayerNorm + projections + mask -> g_Lf, g_Rf (fp32 [S][M])
// ---------------------------------------------------------------------------
__global__ __launch_bounds__(256) void prep_kernel(
    const float* __restrict__ msa, const float* __restrict__ mask,
    const float* __restrict__ gamma, const float* __restrict__ beta,
    const float* __restrict__ wl, const float* __restrict__ wr)
{
    __shared__ float ws[64][65];
    __shared__ float xs[4][64];
    __shared__ float redS[8], redQ[8];

    int tid = threadIdx.x;
    for (int t = tid; t < 2048; t += 256) {
        int o = t >> 6, c = t & 63;
        ws[o][c]      = wl[t];
        ws[32 + o][c] = wr[t];
    }

    int g = tid >> 6;
    int c = tid & 63;
    int row = blockIdx.x * 4 + g;

    float v = msa[row * 64 + c];
    float s = v, q = v * v;
    #pragma unroll
    for (int off = 16; off; off >>= 1) {
        s += __shfl_xor_sync(0xffffffffu, s, off);
        q += __shfl_xor_sync(0xffffffffu, q, off);
    }
    int wid = tid >> 5;
    if ((tid & 31) == 0) { redS[wid] = s; redQ[wid] = q; }
    __syncthreads();

    float S1 = redS[2*g] + redS[2*g + 1];
    float S2 = redQ[2*g] + redQ[2*g + 1];
    float mu  = S1 * (1.0f / 64.0f);
    float var = S2 * (1.0f / 64.0f) - mu * mu;
    float inv = rsqrtf(var + 1e-5f);
    xs[g][c] = (v - mu) * inv * gamma[c] + beta[c];
    __syncthreads();

    float acc = 0.0f;
    const float* xrow = xs[g];
    #pragma unroll 16
    for (int k = 0; k < 64; k++)
        acc += xrow[k] * ws[c][k];
    acc *= mask[row];

    int s_idx = row / R_DIM;
    int r_idx = row - s_idx * R_DIM;
    int o = c & 31;
    if (c < 32) g_Lf[s_idx * M_DIM + r_idx * C_OUTER + o] = acc;
    else        g_Rf[s_idx * M_DIM + r_idx * C_OUTER + o] = acc;
}

// ---------------------------------------------------------------------------
// Kernel 2: bf16 hi/lo split + swizzle into tiled layout
// grid (96, 8, 2): (mtile, kc, L/R)
// ---------------------------------------------------------------------------
__global__ __launch_bounds__(256) void conv_kernel()
{
    __shared__ float Xs[64][128];
    int mt = blockIdx.x, kc = blockIdx.y, sel = blockIdx.z;
    const float* src = sel ? g_Rf : g_Lf;
    uint4* dhi = (sel ? g_Bhi : g_Ahi) + (size_t)(kc * MT_N + mt) * 1024;
    uint4* dlo = (sel ? g_Blo : g_Alo) + (size_t)(kc * MT_N + mt) * 1024;
    int tid = threadIdx.x;

    #pragma unroll
    for (int i = 0; i < 8; i++) {
        int f4 = tid + 256 * i;
        int kl = f4 >> 5;
        int mg = (f4 & 31) << 2;
        *(float4*)&Xs[kl][mg] =
            *(const float4*)&src[(size_t)(kc * 64 + kl) * M_DIM + mt * 128 + mg];
    }
    __syncthreads();

    #pragma unroll
    for (int i = 0; i < 4; i++) {
        int u = tid + 256 * i;
        int r = u >> 3;
        int g16 = u & 7;
        union { unsigned short s[8]; uint4 v; } hi, lo;
        #pragma unroll
        for (int j = 0; j < 8; j++) {
            float f = Xs[g16 * 8 + j][r];
            __nv_bfloat16 h = __float2bfloat16(f);
            float fh = __bfloat162float(h);
            __nv_bfloat16 l = __float2bfloat16(f - fh);
            hi.s[j] = __bfloat16_as_ushort(h);
            lo.s[j] = __bfloat16_as_ushort(l);
        }
        int dst = r * 8 + (g16 ^ (r & 7));
        dhi[dst] = hi.v;
        dlo[dst] = lo.v;
    }
}

// ---------------------------------------------------------------------------
// Kernel 3: norm[b][d] = sum_s mask[s][b] * mask[s][d]
// ---------------------------------------------------------------------------
__global__ __launch_bounds__(256) void norm_kernel(const float* __restrict__ mask)
{
    __shared__ float mb[16][17], md[16][17];
    int tx = threadIdx.x & 15, ty = threadIdx.x >> 4;
    int b0 = blockIdx.x * 16, d0 = blockIdx.y * 16;
    float acc = 0.0f;
    for (int s0 = 0; s0 < S_DIM; s0 += 16) {
        mb[ty][tx] = mask[(s0 + ty) * R_DIM + b0 + tx];
        md[ty][tx] = mask[(s0 + ty) * R_DIM + d0 + tx];
        __syncthreads();
        #pragma unroll
        for (int i = 0; i < 16; i++) acc += mb[i][tx] * md[i][ty];
        __syncthreads();
    }
    g_norm[(b0 + tx) * R_DIM + d0 + ty] = acc;
}

// ---------------------------------------------------------------------------
// Kernel 4: mma.sync bf16 3-pass GEMM (fp32 accum) + SIMT W epilogue
// grid (96, 96), 256 threads, ~131KB dyn smem
// ---------------------------------------------------------------------------
#define CS_STRIDE 132

__global__ __launch_bounds__(256, 1) void mma_fused_kernel(
    const float* __restrict__ W, const float* __restrict__ bias,
    float* __restrict__ out)
{
    extern __shared__ unsigned char dynraw[];
    unsigned raw_u32 = smem_u32(dynraw);
    unsigned base_u32 = (raw_u32 + 1023u) & ~1023u;
    unsigned char* base_ptr = dynraw + (base_u32 - raw_u32);

    int tid = threadIdx.x;
    int wid = tid >> 5, lane = tid & 31;
    int bx = blockIdx.x, by = blockIdx.y;
    int m_off = (wid >> 2) * 64;      // warp m offset (0,64)
    int n_off = (wid & 3) * 32;       // warp n offset (0..96)

    float acc[4][4][4];
    #pragma unroll
    for (int mi = 0; mi < 4; mi++)
        #pragma unroll
        for (int ni = 0; ni < 4; ni++)
            #pragma unroll
            for (int j = 0; j < 4; j++) acc[mi][ni][j] = 0.0f;

    // prefetch chunk 0 into stage 0
    {
        const uint4* s0 = g_Ahi + (size_t)(0 * MT_N + by) * 1024;
        const uint4* s1 = g_Alo + (size_t)(0 * MT_N + by) * 1024;
        const uint4* s2 = g_Bhi + (size_t)(0 * MT_N + bx) * 1024;
        const uint4* s3 = g_Blo + (size_t)(0 * MT_N + bx) * 1024;
        #pragma unroll
        for (int i = 0; i < 4; i++) {
            cp16(base_u32 +         (i * 256 + tid) * 16, s0 + i * 256 + tid);
            cp16(base_u32 + 16384 + (i * 256 + tid) * 16, s1 + i * 256 + tid);
            cp16(base_u32 + 32768 + (i * 256 + tid) * 16, s2 + i * 256 + tid);
            cp16(base_u32 + 49152 + (i * 256 + tid) * 16, s3 + i * 256 + tid);
        }
        CP_COMMIT();
    }

    int rofs = (lane & 7) + 8 * ((lane >> 3) & 1);
    int ghalf = lane >> 4;

    for (int kc = 0; kc < 8; kc++) {
        if (kc < 7) {
            int st2 = (kc + 1) & 1;
            unsigned db = base_u32 + st2 * 65536;
            const uint4* s0 = g_Ahi + (size_t)((kc + 1) * MT_N + by) * 1024;
            const uint4* s1 = g_Alo + (size_t)((kc + 1) * MT_N + by) * 1024;
            const uint4* s2 = g_Bhi + (size_t)((kc + 1) * MT_N + bx) * 1024;
            const uint4* s3 = g_Blo + (size_t)((kc + 1) * MT_N + bx) * 1024;
            #pragma unroll
            for (int i = 0; i < 4; i++) {
                cp16(db +         (i * 256 + tid) * 16, s0 + i * 256 + tid);
                cp16(db + 16384 + (i * 256 + tid) * 16, s1 + i * 256 + tid);
                cp16(db + 32768 + (i * 256 + tid) * 16, s2 + i * 256 + tid);
                cp16(db + 49152 + (i * 256 + tid) * 16, s3 + i * 256 + tid);
            }
            CP_COMMIT();
            CP_WAIT1();
        } else {
            CP_WAIT0();
        }
        __syncthreads();

        unsigned sb = base_u32 + (kc & 1) * 65536;
        #pragma unroll
        for (int ks = 0; ks < 4; ks++) {
            unsigned aH[16], aL[16], bH[8], bL[8];
            int g = 2 * ks + ghalf;
            #pragma unroll
            for (int mi = 0; mi < 4; mi++) {
                int r = m_off + 16 * mi + rofs;
                unsigned idx = (unsigned)(r * 8 + (g ^ (r & 7))) * 16u;
                ldsm4(&aH[mi * 4], sb + idx);
                ldsm4(&aL[mi * 4], sb + 16384 + idx);
            }
            #pragma unroll
            for (int jn = 0; jn < 2; jn++) {
                int r = n_off + 16 * jn + rofs;
                unsigned idx = (unsigned)(r * 8 + (g ^ (r & 7))) * 16u;
                ldsm4(&bH[jn * 4], sb + 32768 + idx);
                ldsm4(&bL[jn * 4], sb + 49152 + idx);
            }
            #pragma unroll
            for (int mi = 0; mi < 4; mi++)
                #pragma unroll
                for (int ni = 0; ni < 4; ni++) {
                    unsigned bh0 = bH[(ni >> 1) * 4 + (ni & 1)];
                    unsigned bh1 = bH[(ni >> 1) * 4 + 2 + (ni & 1)];
                    unsigned bl0 = bL[(ni >> 1) * 4 + (ni & 1)];
                    unsigned bl1 = bL[(ni >> 1) * 4 + 2 + (ni & 1)];
                    mma16816(acc[mi][ni], &aH[mi * 4], bh0, bh1);
                    mma16816(acc[mi][ni], &aH[mi * 4], bl0, bl1);
                    mma16816(acc[mi][ni], &aL[mi * 4], bh0, bh1);
                }
        }
        __syncthreads();
    }

    // ---- store acc tile to smem Cs [128][CS_STRIDE] ----
    float* Cs = (float*)base_ptr;
    float* Ws = (float*)base_ptr + 128 * CS_STRIDE;

    #pragma unroll
    for (int mi = 0; mi < 4; mi++)
        #pragma unroll
        for (int ni = 0; ni < 4; ni++) {
            int m = m_off + 16 * mi + (lane >> 2);
            int n = n_off + 8 * ni + 2 * (lane & 3);
            *(float2*)&Cs[m * CS_STRIDE + n] =
                make_float2(acc[mi][ni][0], acc[mi][ni][1]);
            *(float2*)&Cs[(m + 8) * CS_STRIDE + n] =
                make_float2(acc[mi][ni][2], acc[mi][ni][3]);
        }
    __syncthreads();

    // ---- W contraction epilogue (SIMT) ----
    int q  = tid & 15;
    int pg = (tid >> 4) & 3;
    int ks = tid >> 6;

    float acc2[4][8];
    #pragma unroll
    for (int pp = 0; pp < 4; pp++)
        #pragma unroll
        for (int j = 0; j < 8; j++) acc2[pp][j] = 0.0f;

    for (int mstep = 0; mstep < 8; mstep++) {
        #pragma unroll
        for (int it = 0; it < 16; it++) {
            int t4 = tid + 256 * it;
            int rowW = t4 >> 5;
            int col = (t4 & 31) << 2;
            int ksr = rowW >> 5, rr = rowW & 31;
            *(float4*)&Ws[rowW * 128 + col] =
                *(const float4*)&W[(ksr * 256 + mstep * 32 + rr) * 128 + col];
        }
        __syncthreads();

        const float* WsMe = Ws + ks * 32 * 128;
        int kbase = ks * 256 + mstep * 32;
        #pragma unroll 4
        for (int kk = 0; kk < 32; kk++) {
            int kp = kbase + kk;
            int cc = kp >> 5, ee = kp & 31;
            float w[8];
            #pragma unroll
            for (int j = 0; j < 8; j++) w[j] = WsMe[kk * 128 + q + 16 * j];
            #pragma unroll
            for (int pp = 0; pp < 4; pp++) {
                float pv = Cs[(pg * 32 + cc) * CS_STRIDE + pp * 32 + ee];
                #pragma unroll
                for (int j = 0; j < 8; j++) acc2[pp][j] += pv * w[j];
            }
        }
        __syncthreads();
    }

    // reduce 4 k'-splits via smem (reuse Ws region)
    float* red = Ws;
    #pragma unroll
    for (int pp = 0; pp < 4; pp++)
        #pragma unroll
        for (int j = 0; j < 8; j++)
            red[(ks * 16 + pg * 4 + pp) * 128 + q + 16 * j] = acc2[pp][j];
    __syncthreads();

    int p  = tid >> 4;
    int q2 = tid & 15;
    int bl = p >> 2, dl = p & 3;
    int bg = by * 4 + bl;
    int dg = bx * 4 + dl;
    float invn = 1.0f / (1e-3f + g_norm[bg * R_DIM + dg]);
    #pragma unroll
    for (int j = 0; j < 8; j++) {
        int f = q2 + 16 * j;
        float v = red[0 * 2048 + p * 128 + f]
                + red[1 * 2048 + p * 128 + f]
                + red[2 * 2048 + p * 128 + f]
                + red[3 * 2048 + p * 128 + f];
        out[(bg * R_DIM + dg) * C_OUT + f] = (v + bias[f]) * invn;
    }
}

// ---------------------------------------------------------------------------
extern "C" void kernel_launch(void* const* d_in, const int* in_sizes, int n_in,
                              void* d_out, int out_size)
{
    const float* msa   = (const float*)d_in[0];
    const float* mask  = (const float*)d_in[1];
    const float* gamma = (const float*)d_in[2];
    const float* beta  = (const float*)d_in[3];
    const float* wl    = (const float*)d_in[4];
    const float* wr    = (const float*)d_in[5];
    const float* W     = (const float*)d_in[6];
    const float* bias  = (const float*)d_in[7];
    float* out = (float*)d_out;

    prep_kernel<<<(S_DIM * R_DIM) / 4, 256>>>(msa, mask, gamma, beta, wl, wr);
    conv_kernel<<<dim3(MT_N, KC_N, 2), 256>>>();
    norm_kernel<<<dim3(R_DIM / 16, R_DIM / 16), 256>>>(mask);

    // dyn smem: max(mainloop 2*64KB, epilogue 128*132*4 + 64KB) + 1KB align pad
    int smem_bytes = 128 * CS_STRIDE * 4 + 65536 + 1024;   // 134144
    cudaFuncSetAttribute(mma_fused_kernel,
                         cudaFuncAttributeMaxDynamicSharedMemorySize, smem_bytes);
    mma_fused_kernel<<<dim3(MT_N, MT_N), 256, smem_bytes>>>(W, bias, out);
}

// round 5
// speedup vs baseline: 2.7798x; 1.5153x over previous
#include <cuda_runtime.h>
#include <cuda_bf16.h>

// Problem constants
#define S_DIM 512
#define R_DIM 384
#define C_MSA 64
#define C_OUTER 32
#define C_OUT 128
#define M_DIM (R_DIM * C_OUTER)   // 12288
#define KC_N 8                    // 512 / 64 k-chunks
#define MT_N 96                   // 12288 / 128 m-tiles

// fp32 scratch projections [S][M] (k-major)
__device__ float g_Lf[S_DIM * M_DIM];
__device__ float g_Rf[S_DIM * M_DIM];
__device__ float g_norm[R_DIM * R_DIM];

// Pre-swizzled bf16 tiles: [kc][mtile][128 rows x 128B] as uint4
// element (m,k): tile=(k>>6)*96+(m>>7), r=m&127, g16=(k&63)>>3,
// uint4 index within tile = r*8 + (g16 ^ (r&7)), bf16 lane = k&7
__device__ uint4 g_Ahi[KC_N * MT_N * 1024];
__device__ uint4 g_Alo[KC_N * MT_N * 1024];
__device__ uint4 g_Bhi[KC_N * MT_N * 1024];
__device__ uint4 g_Blo[KC_N * MT_N * 1024];

// Transposed output_w: Wt[f][k'] bf16 hi/lo, k' = c*32+e, row-major [128][1024]
__device__ unsigned short g_Wth[128 * 1024];
__device__ unsigned short g_Wtl[128 * 1024];

// ---------------------------------------------------------------------------
// helpers
// ---------------------------------------------------------------------------
__device__ __forceinline__ unsigned smem_u32(const void* p) {
    unsigned r;
    asm("{ .reg .u64 t; cvta.to.shared.u64 t, %1; cvt.u32.u64 %0, t; }"
        : "=r"(r) : "l"(p));
    return r;
}
__device__ __forceinline__ void cp16(unsigned dst, const void* src) {
    asm volatile("cp.async.cg.shared.global [%0], [%1], 16;"
                 :: "r"(dst), "l"(src) : "memory");
}
#define CP_COMMIT() asm volatile("cp.async.commit_group;" ::: "memory")
#define CP_WAIT1()  asm volatile("cp.async.wait_group 1;" ::: "memory")
#define CP_WAIT0()  asm volatile("cp.async.wait_group 0;" ::: "memory")

__device__ __forceinline__ void ldsm4(unsigned* r, unsigned addr) {
    asm volatile("ldmatrix.sync.aligned.m8n8.x4.shared.b16 {%0,%1,%2,%3}, [%4];"
                 : "=r"(r[0]), "=r"(r[1]), "=r"(r[2]), "=r"(r[3]) : "r"(addr));
}
__device__ __forceinline__ void mma16816(float* c, const unsigned* a,
                                         unsigned b0, unsigned b1) {
    asm volatile("mma.sync.aligned.m16n8k16.row.col.f32.bf16.bf16.f32 "
                 "{%0,%1,%2,%3}, {%4,%5,%6,%7}, {%8,%9}, {%0,%1,%2,%3};"
                 : "+f"(c[0]), "+f"(c[1]), "+f"(c[2]), "+f"(c[3])
                 : "r"(a[0]), "r"(a[1]), "r"(a[2]), "r"(a[3]),
                   "r"(b0), "r"(b1));
}
__device__ __forceinline__ unsigned pack_bf16x2(float hi_f, float lo_f) {
    // returns u32 with low half = bf16(lo_f), high half = bf16(hi_f)
    unsigned r;
    asm("cvt.rn.bf16x2.f32 %0, %1, %2;" : "=r"(r) : "f"(hi_f), "f"(lo_f));
    return r;
}

// ---------------------------------------------------------------------------
// Kernel 1: LayerNorm + projections + mask -> g_Lf, g_Rf (fp32 [S][M])
// ---------------------------------------------------------------------------
__global__ __launch_bounds__(256) void prep_kernel(
    const float* __restrict__ msa, const float* __restrict__ mask,
    const float* __restrict__ gamma, const float* __restrict__ beta,
    const float* __restrict__ wl, const float* __restrict__ wr)
{
    __shared__ float ws[64][65];
    __shared__ float xs[4][64];
    __shared__ float redS[8], redQ[8];

    int tid = threadIdx.x;
    for (int t = tid; t < 2048; t += 256) {
        int o = t >> 6, c = t & 63;
        ws[o][c]      = wl[t];
        ws[32 + o][c] = wr[t];
    }

    int g = tid >> 6;
    int c = tid & 63;
    int row = blockIdx.x * 4 + g;

    float v = msa[row * 64 + c];
    float s = v, q = v * v;
    #pragma unroll
    for (int off = 16; off; off >>= 1) {
        s += __shfl_xor_sync(0xffffffffu, s, off);
        q += __shfl_xor_sync(0xffffffffu, q, off);
    }
    int wid = tid >> 5;
    if ((tid & 31) == 0) { redS[wid] = s; redQ[wid] = q; }
    __syncthreads();

    float S1 = redS[2*g] + redS[2*g + 1];
    float S2 = redQ[2*g] + redQ[2*g + 1];
    float mu  = S1 * (1.0f / 64.0f);
    float var = S2 * (1.0f / 64.0f) - mu * mu;
    float inv = rsqrtf(var + 1e-5f);
    xs[g][c] = (v - mu) * inv * gamma[c] + beta[c];
    __syncthreads();

    float acc = 0.0f;
    const float* xrow = xs[g];
    #pragma unroll 16
    for (int k = 0; k < 64; k++)
        acc += xrow[k] * ws[c][k];
    acc *= mask[row];

    int s_idx = row / R_DIM;
    int r_idx = row - s_idx * R_DIM;
    int o = c & 31;
    if (c < 32) g_Lf[s_idx * M_DIM + r_idx * C_OUTER + o] = acc;
    else        g_Rf[s_idx * M_DIM + r_idx * C_OUTER + o] = acc;
}

// ---------------------------------------------------------------------------
// Kernel 2: bf16 hi/lo split + swizzle into tiled layout
// grid (96, 8, 2): (mtile, kc, L/R)
// ---------------------------------------------------------------------------
__global__ __launch_bounds__(256) void conv_kernel()
{
    __shared__ float Xs[64][128];
    int mt = blockIdx.x, kc = blockIdx.y, sel = blockIdx.z;
    const float* src = sel ? g_Rf : g_Lf;
    uint4* dhi = (sel ? g_Bhi : g_Ahi) + (size_t)(kc * MT_N + mt) * 1024;
    uint4* dlo = (sel ? g_Blo : g_Alo) + (size_t)(kc * MT_N + mt) * 1024;
    int tid = threadIdx.x;

    #pragma unroll
    for (int i = 0; i < 8; i++) {
        int f4 = tid + 256 * i;
        int kl = f4 >> 5;
        int mg = (f4 & 31) << 2;
        *(float4*)&Xs[kl][mg] =
            *(const float4*)&src[(size_t)(kc * 64 + kl) * M_DIM + mt * 128 + mg];
    }
    __syncthreads();

    #pragma unroll
    for (int i = 0; i < 4; i++) {
        int u = tid + 256 * i;
        int r = u >> 3;
        int g16 = u & 7;
        union { unsigned short s[8]; uint4 v; } hi, lo;
        #pragma unroll
        for (int j = 0; j < 8; j++) {
            float f = Xs[g16 * 8 + j][r];
            __nv_bfloat16 h = __float2bfloat16(f);
            float fh = __bfloat162float(h);
            __nv_bfloat16 l = __float2bfloat16(f - fh);
            hi.s[j] = __bfloat16_as_ushort(h);
            lo.s[j] = __bfloat16_as_ushort(l);
        }
        int dst = r * 8 + (g16 ^ (r & 7));
        dhi[dst] = hi.v;
        dlo[dst] = lo.v;
    }
}

// ---------------------------------------------------------------------------
// Kernel 3: norm[b][d] = sum_s mask[s][b] * mask[s][d]
// ---------------------------------------------------------------------------
__global__ __launch_bounds__(256) void norm_kernel(const float* __restrict__ mask)
{
    __shared__ float mb[16][17], md[16][17];
    int tx = threadIdx.x & 15, ty = threadIdx.x >> 4;
    int b0 = blockIdx.x * 16, d0 = blockIdx.y * 16;
    float acc = 0.0f;
    for (int s0 = 0; s0 < S_DIM; s0 += 16) {
        mb[ty][tx] = mask[(s0 + ty) * R_DIM + b0 + tx];
        md[ty][tx] = mask[(s0 + ty) * R_DIM + d0 + tx];
        __syncthreads();
        #pragma unroll
        for (int i = 0; i < 16; i++) acc += mb[i][tx] * md[i][ty];
        __syncthreads();
    }
    g_norm[(b0 + tx) * R_DIM + d0 + ty] = acc;
}

// ---------------------------------------------------------------------------
// Kernel 3b: transpose W [1024][128] -> Wt [128][1024] bf16 hi/lo. grid 32.
// ---------------------------------------------------------------------------
__global__ __launch_bounds__(256) void wtrans_kernel(const float* __restrict__ W)
{
    __shared__ float tile[32][129];
    int b = blockIdx.x;
    int tid = threadIdx.x;
    #pragma unroll
    for (int i = 0; i < 16; i++) {
        int idx = tid + 256 * i;
        int kk = idx >> 7, f = idx & 127;
        tile[kk][f] = W[(b * 32 + kk) * 128 + f];
    }
    __syncthreads();
    int f = tid >> 1, kh = (tid & 1) * 16;
    #pragma unroll
    for (int i = 0; i < 16; i++) {
        int k = kh + i;
        float v = tile[k][f];
        __nv_bfloat16 h = __float2bfloat16(v);
        float fh = __bfloat162float(h);
        __nv_bfloat16 l = __float2bfloat16(v - fh);
        g_Wth[f * 1024 + b * 32 + k] = __bfloat16_as_ushort(h);
        g_Wtl[f * 1024 + b * 32 + k] = __bfloat16_as_ushort(l);
    }
}

// ---------------------------------------------------------------------------
// Kernel 4: mma.sync bf16 3-pass GEMM + tensorized W epilogue
// grid (96, 96), 256 threads, ~193KB dyn smem, 1 CTA/SM
// smem map (after 1KB align): [0,64K) P2h/P2l (epi) | mainloop stage0
//                             [64K,128K) Wt stageB (epi) | mainloop stage1
//                             [128K,192K) Wt stageC (prefetched chunk0)
// ---------------------------------------------------------------------------
__device__ __forceinline__ void load_wt_chunk(unsigned dstbase, int chunk, int tid)
{
    #pragma unroll
    for (int i = 0; i < 8; i++) {
        int s = tid + 256 * i;           // 0..2047
        int f = s >> 4, g = s & 15;
        unsigned off = (unsigned)(f * 256 + ((g ^ (f & 7)) << 4));
        cp16(dstbase + off,         g_Wth + f * 1024 + chunk * 128 + g * 8);
        cp16(dstbase + 32768 + off, g_Wtl + f * 1024 + chunk * 128 + g * 8);
    }
}

__global__ __launch_bounds__(256, 1) void mma_fused_kernel(
    const float* __restrict__ bias, float* __restrict__ out)
{
    extern __shared__ unsigned char dynraw[];
    unsigned raw_u32 = smem_u32(dynraw);
    unsigned base_u32 = (raw_u32 + 1023u) & ~1023u;

    int tid = threadIdx.x;
    int wid = tid >> 5, lane = tid & 31;
    int bx = blockIdx.x, by = blockIdx.y;
    int m_off = (wid >> 2) * 64;
    int n_off = (wid & 3) * 32;

    float acc[4][4][4];
    #pragma unroll
    for (int mi = 0; mi < 4; mi++)
        #pragma unroll
        for (int ni = 0; ni < 4; ni++)
            #pragma unroll
            for (int j = 0; j < 4; j++) acc[mi][ni][j] = 0.0f;

    // Prefetch Wt chunk 0 into stageC (region untouched by mainloop)
    load_wt_chunk(base_u32 + 131072, 0, tid);
    CP_COMMIT();

    // prefetch mainloop chunk 0 into stage 0
    {
        const uint4* s0 = g_Ahi + (size_t)(0 * MT_N + by) * 1024;
        const uint4* s1 = g_Alo + (size_t)(0 * MT_N + by) * 1024;
        const uint4* s2 = g_Bhi + (size_t)(0 * MT_N + bx) * 1024;
        const uint4* s3 = g_Blo + (size_t)(0 * MT_N + bx) * 1024;
        #pragma unroll
        for (int i = 0; i < 4; i++) {
            cp16(base_u32 +         (i * 256 + tid) * 16, s0 + i * 256 + tid);
            cp16(base_u32 + 16384 + (i * 256 + tid) * 16, s1 + i * 256 + tid);
            cp16(base_u32 + 32768 + (i * 256 + tid) * 16, s2 + i * 256 + tid);
            cp16(base_u32 + 49152 + (i * 256 + tid) * 16, s3 + i * 256 + tid);
        }
        CP_COMMIT();
    }

    int rofs = (lane & 7) + 8 * ((lane >> 3) & 1);
    int ghalf = lane >> 4;

    for (int kc = 0; kc < 8; kc++) {
        if (kc < 7) {
            int st2 = (kc + 1) & 1;
            unsigned db = base_u32 + st2 * 65536;
            const uint4* s0 = g_Ahi + (size_t)((kc + 1) * MT_N + by) * 1024;
            const uint4* s1 = g_Alo + (size_t)((kc + 1) * MT_N + by) * 1024;
            const uint4* s2 = g_Bhi + (size_t)((kc + 1) * MT_N + bx) * 1024;
            const uint4* s3 = g_Blo + (size_t)((kc + 1) * MT_N + bx) * 1024;
            #pragma unroll
            for (int i = 0; i < 4; i++) {
                cp16(db +         (i * 256 + tid) * 16, s0 + i * 256 + tid);
                cp16(db + 16384 + (i * 256 + tid) * 16, s1 + i * 256 + tid);
                cp16(db + 32768 + (i * 256 + tid) * 16, s2 + i * 256 + tid);
                cp16(db + 49152 + (i * 256 + tid) * 16, s3 + i * 256 + tid);
            }
            CP_COMMIT();
            CP_WAIT1();
        } else {
            CP_WAIT0();
        }
        __syncthreads();

        unsigned sb = base_u32 + (kc & 1) * 65536;
        #pragma unroll
        for (int ks = 0; ks < 4; ks++) {
            unsigned aH[16], aL[16], bH[8], bL[8];
            int g = 2 * ks + ghalf;
            #pragma unroll
            for (int mi = 0; mi < 4; mi++) {
                int r = m_off + 16 * mi + rofs;
                unsigned idx = (unsigned)(r * 8 + (g ^ (r & 7))) * 16u;
                ldsm4(&aH[mi * 4], sb + idx);
                ldsm4(&aL[mi * 4], sb + 16384 + idx);
            }
            #pragma unroll
            for (int jn = 0; jn < 2; jn++) {
                int r = n_off + 16 * jn + rofs;
                unsigned idx = (unsigned)(r * 8 + (g ^ (r & 7))) * 16u;
                ldsm4(&bH[jn * 4], sb + 32768 + idx);
                ldsm4(&bL[jn * 4], sb + 49152 + idx);
            }
            #pragma unroll
            for (int mi = 0; mi < 4; mi++)
                #pragma unroll
                for (int ni = 0; ni < 4; ni++) {
                    unsigned bh0 = bH[(ni >> 1) * 4 + (ni & 1)];
                    unsigned bh1 = bH[(ni >> 1) * 4 + 2 + (ni & 1)];
                    unsigned bl0 = bL[(ni >> 1) * 4 + (ni & 1)];
                    unsigned bl1 = bL[(ni >> 1) * 4 + 2 + (ni & 1)];
                    mma16816(acc[mi][ni], &aH[mi * 4], bh0, bh1);
                    mma16816(acc[mi][ni], &aH[mi * 4], bl0, bl1);
                    mma16816(acc[mi][ni], &aL[mi * 4], bh0, bh1);
                }
        }
        __syncthreads();
    }

    // ---- Epilogue stage A: prefetch Wt chunk1 into stageB, convert acc->P2 ----
    load_wt_chunk(base_u32 + 65536, 1, tid);
    CP_COMMIT();

    // P2h at [0,32K), P2l at [32K,64K): 16 rows x 2048B, XOR-swizzled 16B groups
    {
        int dl = wid & 3;
        #pragma unroll
        for (int mi = 0; mi < 4; mi++) {
            int p = ((m_off + 16 * mi) >> 5) * 4 + dl;
            int cbase = (16 * mi) & 31;
            int c0 = cbase + (lane >> 2);
            unsigned prow = base_u32 + (unsigned)(p * 2048);
            int psw = p & 7;
            #pragma unroll
            for (int ni = 0; ni < 4; ni++) {
                int e = 8 * ni + 2 * (lane & 3);
                #pragma unroll
                for (int half = 0; half < 2; half++) {
                    int k = (c0 + 8 * half) * 32 + e;
                    float v0 = acc[mi][ni][2 * half];
                    float v1 = acc[mi][ni][2 * half + 1];
                    unsigned hp = pack_bf16x2(v1, v0);
                    float fh0 = __uint_as_float(hp << 16);
                    float fh1 = __uint_as_float(hp & 0xffff0000u);
                    unsigned lp = pack_bf16x2(v1 - fh1, v0 - fh0);
                    unsigned addr = prow + (unsigned)((((k >> 3) ^ psw) << 4) + (k & 7) * 2);
                    asm volatile("st.shared.b32 [%0], %1;" :: "r"(addr), "r"(hp) : "memory");
                    asm volatile("st.shared.b32 [%0], %1;" :: "r"(addr + 32768u), "r"(lp) : "memory");
                }
            }
        }
    }
    __syncthreads();

    // ---- Epilogue stage B: mini-GEMM act[16][128] = P2[16][1024] x Wt^T ----
    int pl = lane & 15;
    int fl = (wid << 4) + pl;
    int sel = lane >> 4;
    int psw = pl & 7, fsw = fl & 7;
    float acc2[2][4];
    #pragma unroll
    for (int ni = 0; ni < 2; ni++)
        #pragma unroll
        for (int j = 0; j < 4; j++) acc2[ni][j] = 0.0f;

    unsigned p2base = base_u32 + (unsigned)(pl * 2048);
    for (int mstep = 0; mstep < 8; mstep++) {
        unsigned stage = base_u32 + ((mstep & 1) ? 65536u : 131072u);
        unsigned frow = stage + (unsigned)(fl * 256);
        #pragma unroll
        for (int ks = 0; ks < 8; ks++) {
            int gA = mstep * 16 + ks * 2 + sel;
            int gB = ks * 2 + sel;
            unsigned aH[4], aL[4], bF[4], bG[4];
            unsigned aaddr = p2base + (unsigned)(((gA ^ psw)) << 4);
            ldsm4(aH, aaddr);
            ldsm4(aL, aaddr + 32768u);
            unsigned baddr = frow + (unsigned)(((gB ^ fsw)) << 4);
            ldsm4(bF, baddr);
            ldsm4(bG, baddr + 32768u);
            #pragma unroll
            for (int ni = 0; ni < 2; ni++) {
                mma16816(acc2[ni], aH, bF[ni], bF[ni + 2]);
                mma16816(acc2[ni], aH, bG[ni], bG[ni + 2]);
                mma16816(acc2[ni], aL, bF[ni], bF[ni + 2]);
            }
        }
        __syncthreads();
        if (mstep < 6) {
            load_wt_chunk(stage, mstep + 2, tid);
            CP_COMMIT();
            CP_WAIT1();
        } else if (mstep == 6) {
            CP_WAIT0();
        }
        if (mstep < 7) __syncthreads();
    }

    // ---- Final store: + bias, / (eps + norm) ----
    {
        int p0 = lane >> 2, p1 = p0 + 8;
        int bg0 = by * 4 + (p0 >> 2), dg0 = bx * 4 + (p0 & 3);
        int bg1 = by * 4 + (p1 >> 2), dg1 = bx * 4 + (p1 & 3);
        float invn0 = 1.0f / (1e-3f + g_norm[bg0 * R_DIM + dg0]);
        float invn1 = 1.0f / (1e-3f + g_norm[bg1 * R_DIM + dg1]);
        size_t row0 = (size_t)(bg0 * R_DIM + dg0) * C_OUT;
        size_t row1 = (size_t)(bg1 * R_DIM + dg1) * C_OUT;
        #pragma unroll
        for (int ni = 0; ni < 2; ni++) {
            int f = (wid << 4) + 8 * ni + 2 * (lane & 3);
            float2 bi = *(const float2*)&bias[f];
            *(float2*)&out[row0 + f] =
                make_float2((acc2[ni][0] + bi.x) * invn0, (acc2[ni][1] + bi.y) * invn0);
            *(float2*)&out[row1 + f] =
                make_float2((acc2[ni][2] + bi.x) * invn1, (acc2[ni][3] + bi.y) * invn1);
        }
    }
}

// ---------------------------------------------------------------------------
extern "C" void kernel_launch(void* const* d_in, const int* in_sizes, int n_in,
                              void* d_out, int out_size)
{
    const float* msa   = (const float*)d_in[0];
    const float* mask  = (const float*)d_in[1];
    const float* gamma = (const float*)d_in[2];
    const float* beta  = (const float*)d_in[3];
    const float* wl    = (const float*)d_in[4];
    const float* wr    = (const float*)d_in[5];
    const float* W     = (const float*)d_in[6];
    const float* bias  = (const float*)d_in[7];
    float* out = (float*)d_out;

    prep_kernel<<<(S_DIM * R_DIM) / 4, 256>>>(msa, mask, gamma, beta, wl, wr);
    wtrans_kernel<<<32, 256>>>(W);
    conv_kernel<<<dim3(MT_N, KC_N, 2), 256>>>();
    norm_kernel<<<dim3(R_DIM / 16, R_DIM / 16), 256>>>(mask);

    // dyn smem: 192KB regions + 1KB align pad
    int smem_bytes = 196608 + 1024;
    cudaFuncSetAttribute(mma_fused_kernel,
                         cudaFuncAttributeMaxDynamicSharedMemorySize, smem_bytes);
    mma_fused_kernel<<<dim3(MT_N, MT_N), 256, smem_bytes>>>(bias, out);
}